// round 1
// baseline (speedup 1.0000x reference)
#include <cuda_runtime.h>
#include <cuda_bf16.h>
#include <stdint.h>

#define B_DIM 2048
#define D_DIM 128
#define C_DIM 100000
#define KNN 10

// Scratch (device globals: allocation-free per harness rules)
__device__ __align__(16) __nv_bfloat16 g_enc_bf16[B_DIM * D_DIM];
__device__ float g_enc_norm[B_DIM];
__device__ __align__(16) __nv_bfloat16 g_mem_bf16[C_DIM * D_DIM];
__device__ float g_mem_norm[C_DIM];
__device__ float g_sq[(size_t)B_DIM * (size_t)C_DIM];   // 819 MB fp32 sq-distances

// ---------------------------------------------------------------------------
// Kernel 1: fused 2-layer encoder. One CTA per batch row, 128 threads.
// Thread j computes output feature j. W[k*D+j] reads are coalesced across j.
// Outputs bf16-quantized enc and its (quantized) squared norm.
// ---------------------------------------------------------------------------
__global__ void encoder_kernel(const float* __restrict__ state,
                               const float* __restrict__ W1, const float* __restrict__ b1,
                               const float* __restrict__ W2, const float* __restrict__ b2) {
    __shared__ float s_in[D_DIM];
    __shared__ float s_h[D_DIM];
    __shared__ float s_red[D_DIM];
    const int b = blockIdx.x;
    const int j = threadIdx.x;

    s_in[j] = state[b * D_DIM + j];
    __syncthreads();

    float acc = b1[j];
#pragma unroll 8
    for (int k = 0; k < D_DIM; k++) acc = fmaf(s_in[k], W1[k * D_DIM + j], acc);
    s_h[j] = fmaxf(acc, 0.0f);
    __syncthreads();

    float acc2 = b2[j];
#pragma unroll 8
    for (int k = 0; k < D_DIM; k++) acc2 = fmaf(s_h[k], W2[k * D_DIM + j], acc2);

    __nv_bfloat16 q = __float2bfloat16(acc2);
    float qf = __bfloat162float(q);
    g_enc_bf16[b * D_DIM + j] = q;
    s_red[j] = qf * qf;
    __syncthreads();
#pragma unroll
    for (int s = 64; s > 0; s >>= 1) {
        if (j < s) s_red[j] += s_red[j + s];
        __syncthreads();
    }
    if (j == 0) g_enc_norm[b] = s_red[0];
}

// ---------------------------------------------------------------------------
// Kernel 2: memory -> bf16 + squared norms. One warp per memory row.
// ---------------------------------------------------------------------------
__global__ void memprep_kernel(const float* __restrict__ memory) {
    const int warp = blockIdx.x * (blockDim.x >> 5) + (threadIdx.x >> 5);
    const int lane = threadIdx.x & 31;
    if (warp >= C_DIM) return;

    const float4 v = ((const float4*)(memory + (size_t)warp * D_DIM))[lane];
    __nv_bfloat16 q0 = __float2bfloat16(v.x);
    __nv_bfloat16 q1 = __float2bfloat16(v.y);
    __nv_bfloat16 q2 = __float2bfloat16(v.z);
    __nv_bfloat16 q3 = __float2bfloat16(v.w);
    float f0 = __bfloat162float(q0), f1 = __bfloat162float(q1);
    float f2 = __bfloat162float(q2), f3 = __bfloat162float(q3);

    __nv_bfloat162* dst = (__nv_bfloat162*)(g_mem_bf16 + (size_t)warp * D_DIM);
    dst[lane * 2 + 0] = __halves2bfloat162(q0, q1);
    dst[lane * 2 + 1] = __halves2bfloat162(q2, q3);

    float sum = f0 * f0 + f1 * f1 + f2 * f2 + f3 * f3;
#pragma unroll
    for (int off = 16; off > 0; off >>= 1)
        sum += __shfl_xor_sync(0xFFFFFFFFu, sum, off);
    if (lane == 0) g_mem_norm[warp] = sum;
}

// ---------------------------------------------------------------------------
// Kernel 3: distance GEMM (bf16 mma.sync, fp32 accum).
// CTA tile 128(M rows of enc) x 128(N rows of memory), K=128 in two 64-chunks.
// 8 warps: 4 along M (32 rows each) x 2 along N (64 cols each).
// Shared stride 88 elems (176B = 44 banks) -> conflict-free fragment loads
// and 16B-aligned vector fills.
// Epilogue: sq = ||e||^2 + ||m||^2 - 2*dot, stored to g_sq.
// ---------------------------------------------------------------------------
#define TILE 128
#define KCHUNK 64
#define SSTR 88

__global__ __launch_bounds__(256) void dist_gemm_kernel() {
    __shared__ __align__(16) __nv_bfloat16 sA[TILE * SSTR];
    __shared__ __align__(16) __nv_bfloat16 sB[TILE * SSTR];

    const int tid = threadIdx.x;
    const int wid = tid >> 5, lane = tid & 31;
    const int g = lane >> 2, t = lane & 3;
    const int wm = wid >> 1, wn = wid & 1;
    const int rowBase = blockIdx.y * TILE;
    const int colBase = blockIdx.x * TILE;

    float acc[2][8][4];
#pragma unroll
    for (int mi = 0; mi < 2; mi++)
#pragma unroll
        for (int nj = 0; nj < 8; nj++)
#pragma unroll
            for (int r = 0; r < 4; r++) acc[mi][nj][r] = 0.0f;

    for (int kc = 0; kc < D_DIM; kc += KCHUNK) {
        if (kc) __syncthreads();   // protect smem from previous iteration's readers
        // Load A chunk: 128 rows x 64 bf16 = 1024 x 16B segments
#pragma unroll
        for (int i = 0; i < 4; i++) {
            int seg = tid + i * 256;
            int row = seg >> 3, s = seg & 7;
            uint4 v = *(const uint4*)(g_enc_bf16 + (size_t)(rowBase + row) * D_DIM + kc + s * 8);
            *(uint4*)(sA + row * SSTR + s * 8) = v;
        }
        // Load B chunk (memory rows), zero-fill out-of-range
#pragma unroll
        for (int i = 0; i < 4; i++) {
            int seg = tid + i * 256;
            int row = seg >> 3, s = seg & 7;
            int col = colBase + row;
            uint4 v = make_uint4(0u, 0u, 0u, 0u);
            if (col < C_DIM)
                v = *(const uint4*)(g_mem_bf16 + (size_t)col * D_DIM + kc + s * 8);
            *(uint4*)(sB + row * SSTR + s * 8) = v;
        }
        __syncthreads();

#pragma unroll
        for (int ks = 0; ks < KCHUNK; ks += 16) {
            uint32_t a[2][4];
#pragma unroll
            for (int mi = 0; mi < 2; mi++) {
                const __nv_bfloat16* base = sA + (wm * 32 + mi * 16 + g) * SSTR + ks + 2 * t;
                a[mi][0] = *(const uint32_t*)(base);
                a[mi][1] = *(const uint32_t*)(base + 8 * SSTR);
                a[mi][2] = *(const uint32_t*)(base + 8);
                a[mi][3] = *(const uint32_t*)(base + 8 * SSTR + 8);
            }
#pragma unroll
            for (int nj = 0; nj < 8; nj++) {
                const __nv_bfloat16* bb = sB + (wn * 64 + nj * 8 + g) * SSTR + ks + 2 * t;
                uint32_t b0 = *(const uint32_t*)(bb);
                uint32_t b1 = *(const uint32_t*)(bb + 8);
#pragma unroll
                for (int mi = 0; mi < 2; mi++) {
                    asm volatile(
                        "mma.sync.aligned.m16n8k16.row.col.f32.bf16.bf16.f32 "
                        "{%0,%1,%2,%3}, {%4,%5,%6,%7}, {%8,%9}, {%0,%1,%2,%3};\n"
                        : "+f"(acc[mi][nj][0]), "+f"(acc[mi][nj][1]),
                          "+f"(acc[mi][nj][2]), "+f"(acc[mi][nj][3])
                        : "r"(a[mi][0]), "r"(a[mi][1]), "r"(a[mi][2]), "r"(a[mi][3]),
                          "r"(b0), "r"(b1));
                }
            }
        }
    }

    // Epilogue: sq = en + mn - 2*dot
#pragma unroll
    for (int mi = 0; mi < 2; mi++) {
        const int r0 = rowBase + wm * 32 + mi * 16 + g;
        const float en0 = g_enc_norm[r0];
        const float en8 = g_enc_norm[r0 + 8];
#pragma unroll
        for (int nj = 0; nj < 8; nj++) {
            const int col = colBase + wn * 64 + nj * 8 + 2 * t;
            if (col < C_DIM) {
                const float mn0 = g_mem_norm[col];
                const float mn1 = g_mem_norm[col + 1];
                float2 v0, v1;
                v0.x = en0 + mn0 - 2.0f * acc[mi][nj][0];
                v0.y = en0 + mn1 - 2.0f * acc[mi][nj][1];
                v1.x = en8 + mn0 - 2.0f * acc[mi][nj][2];
                v1.y = en8 + mn1 - 2.0f * acc[mi][nj][3];
                *(float2*)(g_sq + (size_t)r0 * C_DIM + col) = v0;
                *(float2*)(g_sq + (size_t)(r0 + 8) * C_DIM + col) = v1;
            }
        }
    }
}

// ---------------------------------------------------------------------------
// Kernel 4: per-row top-10 smallest sq -> mean distance.
// 256 threads/row, threshold-guarded insertion into a register-sorted top-10,
// then 3-stage merge (256*10 -> 32*10 -> 10) in shared.
// ---------------------------------------------------------------------------
__device__ __forceinline__ void topk_insert(float (&top)[KNN], float v) {
    if (v < top[KNN - 1]) {
        top[KNN - 1] = v;
#pragma unroll
        for (int i = KNN - 2; i >= 0; i--) {
            if (top[i + 1] < top[i]) {
                float tmp = top[i]; top[i] = top[i + 1]; top[i + 1] = tmp;
            }
        }
    }
}

__global__ void topk_kernel(float* __restrict__ out) {
    __shared__ float svals[256 * KNN];
    __shared__ float swarp[32 * KNN];
    const int row = blockIdx.x;
    const int tid = threadIdx.x;
    const float* sq = g_sq + (size_t)row * C_DIM;

    float top[KNN];
#pragma unroll
    for (int i = 0; i < KNN; i++) top[i] = 3.0e38f;

    for (int c = tid; c < C_DIM; c += 256) topk_insert(top, sq[c]);

#pragma unroll
    for (int i = 0; i < KNN; i++) svals[tid * KNN + i] = top[i];
    __syncthreads();

    if (tid < 32) {
        float t2[KNN];
#pragma unroll
        for (int i = 0; i < KNN; i++) t2[i] = 3.0e38f;
        const int base = tid * 80;   // 2560 / 32
        for (int c = 0; c < 80; c++) topk_insert(t2, svals[base + c]);
#pragma unroll
        for (int i = 0; i < KNN; i++) swarp[tid * KNN + i] = t2[i];
    }
    __syncthreads();

    if (tid == 0) {
        float t3[KNN];
#pragma unroll
        for (int i = 0; i < KNN; i++) t3[i] = 3.0e38f;
        for (int c = 0; c < 32 * KNN; c++) topk_insert(t3, swarp[c]);
        float sum = 0.0f;
#pragma unroll
        for (int i = 0; i < KNN; i++) sum += sqrtf(fmaxf(t3[i], 1e-12f));
        out[row] = sum * (1.0f / KNN);
    }
}

// ---------------------------------------------------------------------------
extern "C" void kernel_launch(void* const* d_in, const int* in_sizes, int n_in,
                              void* d_out, int out_size) {
    const float* state  = (const float*)d_in[0];
    const float* W1     = (const float*)d_in[1];
    const float* b1     = (const float*)d_in[2];
    const float* W2     = (const float*)d_in[3];
    const float* b2     = (const float*)d_in[4];
    const float* memory = (const float*)d_in[5];

    encoder_kernel<<<B_DIM, 128>>>(state, W1, b1, W2, b2);
    memprep_kernel<<<(C_DIM + 7) / 8, 256>>>(memory);

    dim3 grid((C_DIM + TILE - 1) / TILE, B_DIM / TILE);
    dist_gemm_kernel<<<grid, 256>>>();

    topk_kernel<<<B_DIM, 256>>>((float*)d_out);
}

// round 2
// speedup vs baseline: 1.1688x; 1.1688x over previous
#include <cuda_runtime.h>
#include <cuda_bf16.h>
#include <stdint.h>

#define B_DIM 2048
#define D_DIM 128
#define C_DIM 100000
#define KNN 10
#define TILE 128
#define KCHUNK 64
#define SSTR 88
#define SPAD 132
#define NT 782   /* ceil(100000/128) column tiles */

// Scratch (device globals: allocation-free per harness rules)
__device__ __align__(16) __nv_bfloat16 g_enc_bf16[B_DIM * D_DIM];
__device__ float g_enc_norm[B_DIM];
__device__ __align__(16) __nv_bfloat16 g_mem_bf16[C_DIM * D_DIM];
__device__ float g_mem_norm[C_DIM];
__device__ float g_part[(size_t)B_DIM * NT * KNN];   // 64 MB partial top-10 lists

// ---------------------------------------------------------------------------
// Kernel 1: fused 2-layer encoder. One CTA per batch row, 128 threads.
// ---------------------------------------------------------------------------
__global__ void encoder_kernel(const float* __restrict__ state,
                               const float* __restrict__ W1, const float* __restrict__ b1,
                               const float* __restrict__ W2, const float* __restrict__ b2) {
    __shared__ float s_in[D_DIM];
    __shared__ float s_h[D_DIM];
    __shared__ float s_red[D_DIM];
    const int b = blockIdx.x;
    const int j = threadIdx.x;

    s_in[j] = state[b * D_DIM + j];
    __syncthreads();

    float acc = b1[j];
#pragma unroll 8
    for (int k = 0; k < D_DIM; k++) acc = fmaf(s_in[k], W1[k * D_DIM + j], acc);
    s_h[j] = fmaxf(acc, 0.0f);
    __syncthreads();

    float acc2 = b2[j];
#pragma unroll 8
    for (int k = 0; k < D_DIM; k++) acc2 = fmaf(s_h[k], W2[k * D_DIM + j], acc2);

    __nv_bfloat16 q = __float2bfloat16(acc2);
    float qf = __bfloat162float(q);
    g_enc_bf16[b * D_DIM + j] = q;
    s_red[j] = qf * qf;
    __syncthreads();
#pragma unroll
    for (int s = 64; s > 0; s >>= 1) {
        if (j < s) s_red[j] += s_red[j + s];
        __syncthreads();
    }
    if (j == 0) g_enc_norm[b] = s_red[0];
}

// ---------------------------------------------------------------------------
// Kernel 2: memory -> bf16 + squared norms. One warp per memory row.
// ---------------------------------------------------------------------------
__global__ void memprep_kernel(const float* __restrict__ memory) {
    const int warp = blockIdx.x * (blockDim.x >> 5) + (threadIdx.x >> 5);
    const int lane = threadIdx.x & 31;
    if (warp >= C_DIM) return;

    const float4 v = ((const float4*)(memory + (size_t)warp * D_DIM))[lane];
    __nv_bfloat16 q0 = __float2bfloat16(v.x);
    __nv_bfloat16 q1 = __float2bfloat16(v.y);
    __nv_bfloat16 q2 = __float2bfloat16(v.z);
    __nv_bfloat16 q3 = __float2bfloat16(v.w);
    float f0 = __bfloat162float(q0), f1 = __bfloat162float(q1);
    float f2 = __bfloat162float(q2), f3 = __bfloat162float(q3);

    __nv_bfloat162* dst = (__nv_bfloat162*)(g_mem_bf16 + (size_t)warp * D_DIM);
    dst[lane * 2 + 0] = __halves2bfloat162(q0, q1);
    dst[lane * 2 + 1] = __halves2bfloat162(q2, q3);

    float sum = f0 * f0 + f1 * f1 + f2 * f2 + f3 * f3;
#pragma unroll
    for (int off = 16; off > 0; off >>= 1)
        sum += __shfl_xor_sync(0xFFFFFFFFu, sum, off);
    if (lane == 0) g_mem_norm[warp] = sum;
}

// ---------------------------------------------------------------------------
// Sorted-ascending top-K insertion (register array).
// ---------------------------------------------------------------------------
__device__ __forceinline__ void topk_insert(float (&top)[KNN], float v) {
    if (v < top[KNN - 1]) {
        top[KNN - 1] = v;
#pragma unroll
        for (int i = KNN - 2; i >= 0; i--) {
            if (top[i + 1] < top[i]) {
                float tmp = top[i]; top[i] = top[i + 1]; top[i + 1] = tmp;
            }
        }
    }
}

// ---------------------------------------------------------------------------
// Kernel 3: fused distance GEMM + per-tile top-10 epilogue.
// CTA tile 128(M enc rows) x 128(N memory rows), bf16 mma.sync, fp32 accum.
// Epilogue: sq tile -> shared (fp32, stride SPAD), 2 threads/row build a
// per-row top-10 over the 128 tile columns, write 10 floats to g_part.
// Dynamic smem = max(operand stage, fp32 tile) = 67584 B.
// ---------------------------------------------------------------------------
__global__ __launch_bounds__(256) void dist_gemm_kernel() {
    extern __shared__ __align__(16) char dynsmem[];
    __nv_bfloat16* sA = (__nv_bfloat16*)dynsmem;
    __nv_bfloat16* sB = sA + TILE * SSTR;
    float* s_tile = (float*)dynsmem;

    const int tid = threadIdx.x;
    const int wid = tid >> 5, lane = tid & 31;
    const int g = lane >> 2, t = lane & 3;
    const int wm = wid >> 1, wn = wid & 1;
    const int rowBase = blockIdx.y * TILE;
    const int colBase = blockIdx.x * TILE;

    float acc[2][8][4];
#pragma unroll
    for (int mi = 0; mi < 2; mi++)
#pragma unroll
        for (int nj = 0; nj < 8; nj++)
#pragma unroll
            for (int r = 0; r < 4; r++) acc[mi][nj][r] = 0.0f;

    for (int kc = 0; kc < D_DIM; kc += KCHUNK) {
        if (kc) __syncthreads();
#pragma unroll
        for (int i = 0; i < 4; i++) {
            int seg = tid + i * 256;
            int row = seg >> 3, s = seg & 7;
            uint4 v = *(const uint4*)(g_enc_bf16 + (size_t)(rowBase + row) * D_DIM + kc + s * 8);
            *(uint4*)(sA + row * SSTR + s * 8) = v;
        }
#pragma unroll
        for (int i = 0; i < 4; i++) {
            int seg = tid + i * 256;
            int row = seg >> 3, s = seg & 7;
            int col = colBase + row;
            uint4 v = make_uint4(0u, 0u, 0u, 0u);
            if (col < C_DIM)
                v = *(const uint4*)(g_mem_bf16 + (size_t)col * D_DIM + kc + s * 8);
            *(uint4*)(sB + row * SSTR + s * 8) = v;
        }
        __syncthreads();

#pragma unroll
        for (int ks = 0; ks < KCHUNK; ks += 16) {
            uint32_t a[2][4];
#pragma unroll
            for (int mi = 0; mi < 2; mi++) {
                const __nv_bfloat16* base = sA + (wm * 32 + mi * 16 + g) * SSTR + ks + 2 * t;
                a[mi][0] = *(const uint32_t*)(base);
                a[mi][1] = *(const uint32_t*)(base + 8 * SSTR);
                a[mi][2] = *(const uint32_t*)(base + 8);
                a[mi][3] = *(const uint32_t*)(base + 8 * SSTR + 8);
            }
#pragma unroll
            for (int nj = 0; nj < 8; nj++) {
                const __nv_bfloat16* bb = sB + (wn * 64 + nj * 8 + g) * SSTR + ks + 2 * t;
                uint32_t b0 = *(const uint32_t*)(bb);
                uint32_t b1 = *(const uint32_t*)(bb + 8);
#pragma unroll
                for (int mi = 0; mi < 2; mi++) {
                    asm volatile(
                        "mma.sync.aligned.m16n8k16.row.col.f32.bf16.bf16.f32 "
                        "{%0,%1,%2,%3}, {%4,%5,%6,%7}, {%8,%9}, {%0,%1,%2,%3};\n"
                        : "+f"(acc[mi][nj][0]), "+f"(acc[mi][nj][1]),
                          "+f"(acc[mi][nj][2]), "+f"(acc[mi][nj][3])
                        : "r"(a[mi][0]), "r"(a[mi][1]), "r"(a[mi][2]), "r"(a[mi][3]),
                          "r"(b0), "r"(b1));
                }
            }
        }
    }

    // ---- Epilogue: sq tile -> shared (fp32) ----
    __syncthreads();   // all operand reads done; safe to repurpose smem
#pragma unroll
    for (int mi = 0; mi < 2; mi++) {
        const int r0 = wm * 32 + mi * 16 + g;   // local rows r0, r0+8
        const float en0 = g_enc_norm[rowBase + r0];
        const float en8 = g_enc_norm[rowBase + r0 + 8];
#pragma unroll
        for (int nj = 0; nj < 8; nj++) {
            const int cl = wn * 64 + nj * 8 + 2 * t;
            const int col = colBase + cl;
            float2 v0, v1;
            if (col < C_DIM) {   // C_DIM even: pair never straddles the edge
                const float mn0 = g_mem_norm[col];
                const float mn1 = g_mem_norm[col + 1];
                v0.x = en0 + mn0 - 2.0f * acc[mi][nj][0];
                v0.y = en0 + mn1 - 2.0f * acc[mi][nj][1];
                v1.x = en8 + mn0 - 2.0f * acc[mi][nj][2];
                v1.y = en8 + mn1 - 2.0f * acc[mi][nj][3];
            } else {
                v0.x = v0.y = v1.x = v1.y = 3.0e38f;
            }
            *(float2*)(s_tile + (size_t)r0 * SPAD + cl) = v0;
            *(float2*)(s_tile + (size_t)(r0 + 8) * SPAD + cl) = v1;
        }
    }
    __syncthreads();

    // ---- Per-row top-10 over this tile: 2 threads/row, 64 cols each ----
    const int srow = tid >> 1, shalf = tid & 1;
    float top[KNN];
#pragma unroll
    for (int i = 0; i < KNN; i++) top[i] = 3.0e38f;
    const float* bp = s_tile + (size_t)srow * SPAD + shalf * 64;
#pragma unroll 8
    for (int j = 0; j < 64; j++) topk_insert(top, bp[j]);
    __syncthreads();

    // odd threads publish their list; even threads merge + write out
    if (shalf) {
#pragma unroll
        for (int i = 0; i < KNN; i++) s_tile[srow * KNN + i] = top[i];
    }
    __syncthreads();
    if (!shalf) {
        const float* q = s_tile + srow * KNN;
#pragma unroll
        for (int i = 0; i < KNN; i++) topk_insert(top, q[i]);
        float* dst = g_part + ((size_t)(rowBase + srow) * NT + blockIdx.x) * KNN;
#pragma unroll
        for (int i = 0; i < KNN; i++) dst[i] = top[i];
    }
}

// ---------------------------------------------------------------------------
// Kernel 4: merge NT per-tile top-10 lists per row -> mean of 10 smallest dists.
// ---------------------------------------------------------------------------
__global__ void reduce_topk(float* __restrict__ out) {
    __shared__ float svals[256 * KNN];
    __shared__ float swarp[32 * KNN];
    const int row = blockIdx.x;
    const int tid = threadIdx.x;
    const float* p = g_part + (size_t)row * NT * KNN;

    float top[KNN];
#pragma unroll
    for (int i = 0; i < KNN; i++) top[i] = 3.0e38f;

    for (int c = tid; c < NT * KNN; c += 256) topk_insert(top, p[c]);

#pragma unroll
    for (int i = 0; i < KNN; i++) svals[tid * KNN + i] = top[i];
    __syncthreads();

    if (tid < 32) {
        float t2[KNN];
#pragma unroll
        for (int i = 0; i < KNN; i++) t2[i] = 3.0e38f;
        const int base = tid * 80;
        for (int c = 0; c < 80; c++) topk_insert(t2, svals[base + c]);
#pragma unroll
        for (int i = 0; i < KNN; i++) swarp[tid * KNN + i] = t2[i];
    }
    __syncthreads();

    if (tid == 0) {
        float t3[KNN];
#pragma unroll
        for (int i = 0; i < KNN; i++) t3[i] = 3.0e38f;
        for (int c = 0; c < 32 * KNN; c++) topk_insert(t3, swarp[c]);
        float sum = 0.0f;
#pragma unroll
        for (int i = 0; i < KNN; i++) sum += sqrtf(fmaxf(t3[i], 1e-12f));
        out[row] = sum * (1.0f / KNN);
    }
}

// ---------------------------------------------------------------------------
#define SMEM_EPI (TILE * SPAD * 4)   /* 67584 > operand stage 45056 */

extern "C" void kernel_launch(void* const* d_in, const int* in_sizes, int n_in,
                              void* d_out, int out_size) {
    const float* state  = (const float*)d_in[0];
    const float* W1     = (const float*)d_in[1];
    const float* b1     = (const float*)d_in[2];
    const float* W2     = (const float*)d_in[3];
    const float* b2     = (const float*)d_in[4];
    const float* memory = (const float*)d_in[5];

    cudaFuncSetAttribute(dist_gemm_kernel,
                         cudaFuncAttributeMaxDynamicSharedMemorySize, SMEM_EPI);

    encoder_kernel<<<B_DIM, 128>>>(state, W1, b1, W2, b2);
    memprep_kernel<<<(C_DIM + 7) / 8, 256>>>(memory);

    dim3 grid(NT, B_DIM / TILE);
    dist_gemm_kernel<<<grid, 256, SMEM_EPI>>>();

    reduce_topk<<<B_DIM, 256>>>((float*)d_out);
}

// round 4
// speedup vs baseline: 1.2766x; 1.0923x over previous
#include <cuda_runtime.h>
#include <cuda_bf16.h>
#include <stdint.h>

#define B_DIM 2048
#define D_DIM 128
#define C_DIM 100000
#define KNN 10
#define TILE 128
#define SPAD 132
#define NT 782   /* ceil(100000/128) column tiles */
#define MT 16    /* 2048/128 row tiles */

// Scratch (device globals: allocation-free per harness rules)
__device__ __align__(16) __nv_bfloat16 g_enc_bf16[B_DIM * D_DIM];
__device__ float g_enc_norm[B_DIM];
__device__ __align__(16) __nv_bfloat16 g_mem_bf16[C_DIM * D_DIM];
__device__ float g_mem_norm[C_DIM];
__device__ __align__(16) float g_part[(size_t)B_DIM * NT * KNN];  // 64 MB partials

// ---------------------------------------------------------------------------
__device__ __forceinline__ uint32_t smem_u32(const void* p) {
    uint32_t a;
    asm("{ .reg .u64 t; cvta.to.shared.u64 t, %1; cvt.u32.u64 %0, t; }" : "=r"(a) : "l"(p));
    return a;
}
__device__ __forceinline__ void ldsm_x4(uint32_t* r, uint32_t addr) {
    asm volatile("ldmatrix.sync.aligned.m8n8.x4.shared.b16 {%0,%1,%2,%3}, [%4];"
                 : "=r"(r[0]), "=r"(r[1]), "=r"(r[2]), "=r"(r[3]) : "r"(addr));
}
__device__ __forceinline__ void cp16(uint32_t dst, const void* src) {
    asm volatile("cp.async.cg.shared.global [%0], [%1], 16;" :: "r"(dst), "l"(src));
}
__device__ __forceinline__ void cp16z(uint32_t dst, const void* src, int srcsize) {
    asm volatile("cp.async.cg.shared.global [%0], [%1], 16, %2;"
                 :: "r"(dst), "l"(src), "r"(srcsize));
}

// ---------------------------------------------------------------------------
// Kernel 1: fused 2-layer encoder (one CTA per batch row).
// ---------------------------------------------------------------------------
__global__ void encoder_kernel(const float* __restrict__ state,
                               const float* __restrict__ W1, const float* __restrict__ b1,
                               const float* __restrict__ W2, const float* __restrict__ b2) {
    __shared__ float s_in[D_DIM];
    __shared__ float s_h[D_DIM];
    __shared__ float s_red[D_DIM];
    const int b = blockIdx.x;
    const int j = threadIdx.x;

    s_in[j] = state[b * D_DIM + j];
    __syncthreads();

    float acc = b1[j];
#pragma unroll 8
    for (int k = 0; k < D_DIM; k++) acc = fmaf(s_in[k], W1[k * D_DIM + j], acc);
    s_h[j] = fmaxf(acc, 0.0f);
    __syncthreads();

    float acc2 = b2[j];
#pragma unroll 8
    for (int k = 0; k < D_DIM; k++) acc2 = fmaf(s_h[k], W2[k * D_DIM + j], acc2);

    __nv_bfloat16 q = __float2bfloat16(acc2);
    float qf = __bfloat162float(q);
    g_enc_bf16[b * D_DIM + j] = q;
    s_red[j] = qf * qf;
    __syncthreads();
#pragma unroll
    for (int s = 64; s > 0; s >>= 1) {
        if (j < s) s_red[j] += s_red[j + s];
        __syncthreads();
    }
    if (j == 0) g_enc_norm[b] = s_red[0];
}

// ---------------------------------------------------------------------------
// Kernel 2: memory -> bf16 + squared norms. One warp per memory row.
// ---------------------------------------------------------------------------
__global__ void memprep_kernel(const float* __restrict__ memory) {
    const int warp = blockIdx.x * (blockDim.x >> 5) + (threadIdx.x >> 5);
    const int lane = threadIdx.x & 31;
    if (warp >= C_DIM) return;

    const float4 v = ((const float4*)(memory + (size_t)warp * D_DIM))[lane];
    __nv_bfloat16 q0 = __float2bfloat16(v.x);
    __nv_bfloat16 q1 = __float2bfloat16(v.y);
    __nv_bfloat16 q2 = __float2bfloat16(v.z);
    __nv_bfloat16 q3 = __float2bfloat16(v.w);
    float f0 = __bfloat162float(q0), f1 = __bfloat162float(q1);
    float f2 = __bfloat162float(q2), f3 = __bfloat162float(q3);

    __nv_bfloat162* dst = (__nv_bfloat162*)(g_mem_bf16 + (size_t)warp * D_DIM);
    dst[lane * 2 + 0] = __halves2bfloat162(q0, q1);
    dst[lane * 2 + 1] = __halves2bfloat162(q2, q3);

    float sum = f0 * f0 + f1 * f1 + f2 * f2 + f3 * f3;
#pragma unroll
    for (int off = 16; off > 0; off >>= 1)
        sum += __shfl_xor_sync(0xFFFFFFFFu, sum, off);
    if (lane == 0) g_mem_norm[warp] = sum;
}

// ---------------------------------------------------------------------------
__device__ __forceinline__ void topk_insert(float (&top)[KNN], float v) {
    if (v < top[KNN - 1]) {
        top[KNN - 1] = v;
#pragma unroll
        for (int i = KNN - 2; i >= 0; i--) {
            if (top[i + 1] < top[i]) {
                float tmp = top[i]; top[i] = top[i + 1]; top[i + 1] = tmp;
            }
        }
    }
}

// ---------------------------------------------------------------------------
// Kernel 3: distance GEMM (mma.sync bf16) + fused per-tile top-10.
// 128x128x128 tile, 8 warps (4 M x 2 N), full-K single-stage smem.
// Smem layout per operand: (row, seg) -> 16B unit  row*16 + (seg ^ (row&7)),
// conflict-free for cp.async stores and ldmatrix loads.
// Fragments via ldmatrix.x4. Epilogue: sq tile -> smem fp32, 2 thr/row top-10.
// ---------------------------------------------------------------------------
__global__ void __launch_bounds__(256) dist_gemm_kernel() {
    extern __shared__ __align__(1024) char smem[];
    const uint32_t sA = smem_u32(smem);
    const uint32_t sB = sA + 32768;
    float* s_tile = (float*)smem;

    const int tid = threadIdx.x;
    const int wid = tid >> 5, lane = tid & 31;
    const int g = lane >> 2, t = lane & 3;
    const int wm = wid >> 1, wn = wid & 1;
    const int rowBase = blockIdx.y * TILE;
    const int colBase = blockIdx.x * TILE;

    // ---- stage A and B tiles (full K=128) via cp.async ----
#pragma unroll
    for (int i = 0; i < 8; i++) {
        int idx = tid + i * 256;
        int row = idx >> 4, s = idx & 15;
        uint32_t dst = sA + ((row * 16 + (s ^ (row & 7))) << 4);
        cp16(dst, g_enc_bf16 + (size_t)(rowBase + row) * D_DIM + s * 8);
    }
#pragma unroll
    for (int i = 0; i < 8; i++) {
        int idx = tid + i * 256;
        int row = idx >> 4, s = idx & 15;
        uint32_t dst = sB + ((row * 16 + (s ^ (row & 7))) << 4);
        int col = colBase + row;
        int ccol = (col < C_DIM) ? col : (C_DIM - 1);
        cp16z(dst, g_mem_bf16 + (size_t)ccol * D_DIM + s * 8, (col < C_DIM) ? 16 : 0);
    }
    asm volatile("cp.async.commit_group;");
    asm volatile("cp.async.wait_group 0;" ::: "memory");
    __syncthreads();

    // ---- fragment addressing ----
    const int m7 = lane & 7;
    const int asel = lane >> 4;                    // 0/1: k-seg select for A
    const int bsel = (lane >> 3) & 1;              // 0/1: k-seg select for B
    const uint32_t aoff0 = sA + ((wm * 32 + (lane & 15)) << 8);
    const uint32_t aoff1 = aoff0 + (16 << 8);
    uint32_t boff[4];
#pragma unroll
    for (int p = 0; p < 4; p++)
        boff[p] = sB + ((wn * 64 + p * 16 + m7 + ((lane >> 4) & 1) * 8) << 8);

    float acc[2][8][4];
#pragma unroll
    for (int mi = 0; mi < 2; mi++)
#pragma unroll
        for (int nj = 0; nj < 8; nj++)
#pragma unroll
            for (int r = 0; r < 4; r++) acc[mi][nj][r] = 0.0f;

    // ---- mainloop: 8 k-steps of m16n8k16 ----
#pragma unroll
    for (int ks = 0; ks < 8; ks++) {
        const uint32_t sa = (uint32_t)(((2 * ks + asel) ^ m7) << 4);
        const uint32_t sb = (uint32_t)(((2 * ks + bsel) ^ m7) << 4);
        uint32_t a0[4], a1[4];
        ldsm_x4(a0, aoff0 + sa);
        ldsm_x4(a1, aoff1 + sa);
#pragma unroll
        for (int p = 0; p < 4; p++) {
            uint32_t b[4];
            ldsm_x4(b, boff[p] + sb);
#pragma unroll
            for (int h = 0; h < 2; h++) {   // nj = 2p+h, B regs {b[2h], b[2h+1]}
                asm volatile(
                    "mma.sync.aligned.m16n8k16.row.col.f32.bf16.bf16.f32 "
                    "{%0,%1,%2,%3}, {%4,%5,%6,%7}, {%8,%9}, {%0,%1,%2,%3};\n"
                    : "+f"(acc[0][2 * p + h][0]), "+f"(acc[0][2 * p + h][1]),
                      "+f"(acc[0][2 * p + h][2]), "+f"(acc[0][2 * p + h][3])
                    : "r"(a0[0]), "r"(a0[1]), "r"(a0[2]), "r"(a0[3]),
                      "r"(b[2 * h]), "r"(b[2 * h + 1]));
                asm volatile(
                    "mma.sync.aligned.m16n8k16.row.col.f32.bf16.bf16.f32 "
                    "{%0,%1,%2,%3}, {%4,%5,%6,%7}, {%8,%9}, {%0,%1,%2,%3};\n"
                    : "+f"(acc[1][2 * p + h][0]), "+f"(acc[1][2 * p + h][1]),
                      "+f"(acc[1][2 * p + h][2]), "+f"(acc[1][2 * p + h][3])
                    : "r"(a1[0]), "r"(a1[1]), "r"(a1[2]), "r"(a1[3]),
                      "r"(b[2 * h]), "r"(b[2 * h + 1]));
            }
        }
    }

    // ---- epilogue: sq tile -> shared fp32 ----
    __syncthreads();   // all smem operand reads done; safe to repurpose
#pragma unroll
    for (int mi = 0; mi < 2; mi++) {
        const int r0 = wm * 32 + mi * 16 + g;
        const float en0 = g_enc_norm[rowBase + r0];
        const float en8 = g_enc_norm[rowBase + r0 + 8];
#pragma unroll
        for (int nj = 0; nj < 8; nj++) {
            const int cl = wn * 64 + nj * 8 + 2 * t;
            const int col = colBase + cl;
            float2 v0, v1;
            if (col < C_DIM) {   // C_DIM even: pair never straddles the edge
                const float mn0 = g_mem_norm[col];
                const float mn1 = g_mem_norm[col + 1];
                v0.x = en0 + mn0 - 2.0f * acc[mi][nj][0];
                v0.y = en0 + mn1 - 2.0f * acc[mi][nj][1];
                v1.x = en8 + mn0 - 2.0f * acc[mi][nj][2];
                v1.y = en8 + mn1 - 2.0f * acc[mi][nj][3];
            } else {
                v0.x = v0.y = v1.x = v1.y = 3.0e38f;
            }
            *(float2*)(s_tile + (size_t)r0 * SPAD + cl) = v0;
            *(float2*)(s_tile + (size_t)(r0 + 8) * SPAD + cl) = v1;
        }
    }
    __syncthreads();

    // ---- per-row top-10: 2 threads/row, 64 cols each ----
    const int srow = tid >> 1, shalf = tid & 1;
    float top[KNN];
#pragma unroll
    for (int i = 0; i < KNN; i++) top[i] = 3.0e38f;
    const float* bp = s_tile + (size_t)srow * SPAD + shalf * 64;
#pragma unroll 8
    for (int j = 0; j < 64; j++) topk_insert(top, bp[j]);
    __syncthreads();

    if (shalf) {
#pragma unroll
        for (int i = 0; i < KNN; i++) s_tile[srow * KNN + i] = top[i];
    }
    __syncthreads();
    if (!shalf) {
        const float* q = s_tile + srow * KNN;
#pragma unroll
        for (int i = 0; i < KNN; i++) topk_insert(top, q[i]);
        float* dst = g_part + ((size_t)(rowBase + srow) * NT + blockIdx.x) * KNN;
#pragma unroll
        for (int i = 0; i < KNN; i++) dst[i] = top[i];
    }
}

// ---------------------------------------------------------------------------
// Kernel 4: merge NT per-tile top-10 lists per row (float4 loads).
// NT*KNN = 7820 = 4 * 1955.
// ---------------------------------------------------------------------------
__global__ void reduce_topk(float* __restrict__ out) {
    __shared__ float svals[256 * KNN];
    __shared__ float swarp[32 * KNN];
    const int row = blockIdx.x;
    const int tid = threadIdx.x;
    const float4* p4 = (const float4*)(g_part + (size_t)row * NT * KNN);

    float top[KNN];
#pragma unroll
    for (int i = 0; i < KNN; i++) top[i] = 3.0e38f;

    for (int c = tid; c < 1955; c += 256) {
        float4 v = p4[c];
        topk_insert(top, v.x);
        topk_insert(top, v.y);
        topk_insert(top, v.z);
        topk_insert(top, v.w);
    }

#pragma unroll
    for (int i = 0; i < KNN; i++) svals[tid * KNN + i] = top[i];
    __syncthreads();

    if (tid < 32) {
        float t2[KNN];
#pragma unroll
        for (int i = 0; i < KNN; i++) t2[i] = 3.0e38f;
        const int base = tid * 80;
        for (int c = 0; c < 80; c++) topk_insert(t2, svals[base + c]);
#pragma unroll
        for (int i = 0; i < KNN; i++) swarp[tid * KNN + i] = t2[i];
    }
    __syncthreads();

    if (tid == 0) {
        float t3[KNN];
#pragma unroll
        for (int i = 0; i < KNN; i++) t3[i] = 3.0e38f;
        for (int c = 0; c < 32 * KNN; c++) topk_insert(t3, swarp[c]);
        float sum = 0.0f;
#pragma unroll
        for (int i = 0; i < KNN; i++) sum += sqrtf(fmaxf(t3[i], 1e-12f));
        out[row] = sum * (1.0f / KNN);
    }
}

// ---------------------------------------------------------------------------
#define SMEM_SZ (TILE * SPAD * 4)   /* 67584 >= 65536 operand bytes */

extern "C" void kernel_launch(void* const* d_in, const int* in_sizes, int n_in,
                              void* d_out, int out_size) {
    const float* state  = (const float*)d_in[0];
    const float* W1     = (const float*)d_in[1];
    const float* b1     = (const float*)d_in[2];
    const float* W2     = (const float*)d_in[3];
    const float* b2     = (const float*)d_in[4];
    const float* memory = (const float*)d_in[5];

    cudaFuncSetAttribute(dist_gemm_kernel,
                         cudaFuncAttributeMaxDynamicSharedMemorySize, SMEM_SZ);

    encoder_kernel<<<B_DIM, 128>>>(state, W1, b1, W2, b2);
    memprep_kernel<<<(C_DIM + 7) / 8, 256>>>(memory);

    dim3 grid(NT, MT);
    dist_gemm_kernel<<<grid, 256, SMEM_SZ>>>();

    reduce_topk<<<B_DIM, 256>>>((float*)d_out);
}